// round 3
// baseline (speedup 1.0000x reference)
#include <cuda_runtime.h>

// LSTM: BATCH=4096, SEQ=999, INPUT=1, HIDDEN=51, OUTPUT=1, future=0
// gates (PyTorch order i,f,g,o):
//   gates = x_t * W_ih^T + b_ih + h * W_hh^T + b_hh
//   c = sigmoid(f)*c + sigmoid(i)*tanh(g);  h = sigmoid(o)*tanh(c)
//   y_t = h . W_fc + b_fc
//
// Strategy: persistent per-CTA LSTM over all 999 steps. Each CTA owns
// B_TILE=4 batch rows; thread (b, j) owns hidden unit j for batch b and
// computes all 4 gate rows (j, 51+j, 102+j, 153+j) each step by streaming
// W_hh rows and the shared h vector via LDS.128 (row pitch padded to 52
// floats -> conflict-free banking). h double-buffered in SMEM -> one
// __syncthreads per step. Compute-bound on the fp32 FMA pipe.

#define HID     51
#define HPAD    52      // 51 padded to multiple of 4 (pad column = 0)
#define G4      204     // 4*HID
#define BT      4       // batch elements per CTA (divides 4096)
#define SEQLEN  999
#define NTHR    204     // BT * HID
#define BATCH   4096

__device__ __forceinline__ float fast_sigmoid(float x) {
    // 1 / (1 + 2^(-x*log2 e))
    float e;
    asm("ex2.approx.f32 %0, %1;" : "=f"(e) : "f"(x * -1.4426950408889634f));
    float r;
    asm("rcp.approx.f32 %0, %1;" : "=f"(r) : "f"(e + 1.0f));
    return r;
}

__device__ __forceinline__ float fast_tanh(float x) {
    // tanh(x) = 2*sigmoid(2x) - 1
    float s = fast_sigmoid(x + x);
    return fmaf(2.0f, s, -1.0f);
}

__global__ __launch_bounds__(NTHR)
void lstm_kernel(const float* __restrict__ input,   // (B, SEQ, 1)
                 const float* __restrict__ W_ih,    // (4H, 1)
                 const float* __restrict__ W_hh,    // (4H, H)
                 const float* __restrict__ b_ih,    // (4H)
                 const float* __restrict__ b_hh,    // (4H)
                 const float* __restrict__ W_fc,    // (1, H)
                 const float* __restrict__ b_fc,    // (1)
                 float* __restrict__ out)           // (B, SEQ, 1)
{
    __shared__ __align__(16) float Wsh[G4 * HPAD];       // 42432 B
    __shared__ __align__(16) float hsh[2][BT][HPAD];     // 1664 B, double-buffered
    __shared__ float bias_sh[G4];
    __shared__ float wih_sh[G4];
    __shared__ __align__(16) float wfc_sh[HPAD];

    const int tid = threadIdx.x;

    // ---- one-time CTA init ----
    for (int idx = tid; idx < G4 * HPAD; idx += NTHR) {
        int g = idx / HPAD;
        int k = idx - g * HPAD;
        Wsh[idx] = (k < HID) ? W_hh[g * HID + k] : 0.0f;
    }
    if (tid < G4) {
        bias_sh[tid] = b_ih[tid] + b_hh[tid];
        wih_sh[tid]  = W_ih[tid];
    }
    if (tid < HPAD) wfc_sh[tid] = (tid < HID) ? W_fc[tid] : 0.0f;
    for (int idx = tid; idx < 2 * BT * HPAD; idx += NTHR)
        (&hsh[0][0][0])[idx] = 0.0f;   // h0 = 0 (and pad columns stay 0)
    __syncthreads();

    const int b  = tid & (BT - 1);     // 0..3
    const int j  = tid >> 2;           // 0..50
    const int bg = blockIdx.x * BT + b;

    const float* __restrict__ xp = input + bg * SEQLEN;
    float* __restrict__ yp = out + bg * SEQLEN;   // valid for tid<BT (b==tid)

    // loop-invariant per-thread weights
    const float wih0 = wih_sh[j];
    const float wih1 = wih_sh[j + HID];
    const float wih2 = wih_sh[j + 2 * HID];
    const float wih3 = wih_sh[j + 3 * HID];
    const float bb0  = bias_sh[j];
    const float bb1  = bias_sh[j + HID];
    const float bb2  = bias_sh[j + 2 * HID];
    const float bb3  = bias_sh[j + 3 * HID];
    const float bfc  = b_fc[0];

    const float* __restrict__ w0p = Wsh + (j            ) * HPAD;
    const float* __restrict__ w1p = Wsh + (j +     HID  ) * HPAD;
    const float* __restrict__ w2p = Wsh + (j + 2 * HID  ) * HPAD;
    const float* __restrict__ w3p = Wsh + (j + 3 * HID  ) * HPAD;

    float c = 0.0f;

    for (int t = 0; t < SEQLEN; t++) {
        const float x = __ldg(xp + t);
        float a0 = fmaf(x, wih0, bb0);
        float a1 = fmaf(x, wih1, bb1);
        float a2 = fmaf(x, wih2, bb2);
        float a3 = fmaf(x, wih3, bb3);

        const float* __restrict__ cur = hsh[t & 1][b];

        #pragma unroll
        for (int kk = 0; kk < HPAD; kk += 4) {
            float4 hv = *reinterpret_cast<const float4*>(cur + kk);
            float4 w0 = *reinterpret_cast<const float4*>(w0p + kk);
            float4 w1 = *reinterpret_cast<const float4*>(w1p + kk);
            float4 w2 = *reinterpret_cast<const float4*>(w2p + kk);
            float4 w3 = *reinterpret_cast<const float4*>(w3p + kk);
            a0 = fmaf(w0.x, hv.x, a0); a0 = fmaf(w0.y, hv.y, a0);
            a0 = fmaf(w0.z, hv.z, a0); a0 = fmaf(w0.w, hv.w, a0);
            a1 = fmaf(w1.x, hv.x, a1); a1 = fmaf(w1.y, hv.y, a1);
            a1 = fmaf(w1.z, hv.z, a1); a1 = fmaf(w1.w, hv.w, a1);
            a2 = fmaf(w2.x, hv.x, a2); a2 = fmaf(w2.y, hv.y, a2);
            a2 = fmaf(w2.z, hv.z, a2); a2 = fmaf(w2.w, hv.w, a2);
            a3 = fmaf(w3.x, hv.x, a3); a3 = fmaf(w3.y, hv.y, a3);
            a3 = fmaf(w3.z, hv.z, a3); a3 = fmaf(w3.w, hv.w, a3);
        }

        const float ig = fast_sigmoid(a0);
        const float fg = fast_sigmoid(a1);
        const float gg = fast_tanh(a2);
        const float og = fast_sigmoid(a3);
        c = fmaf(fg, c, ig * gg);
        const float hn = og * fast_tanh(c);

        hsh[(t + 1) & 1][b][j] = hn;
        __syncthreads();
        // Safe with a single barrier: next iteration writes buffer (t&1)
        // while stragglers only ever read buffer ((t+1)&1) here.

        if (tid < BT) {   // b == tid, j == 0: per-batch output dot
            const float* __restrict__ hb = hsh[(t + 1) & 1][tid];
            float s0 = 0.f, s1 = 0.f, s2 = 0.f, s3 = 0.f;
            #pragma unroll
            for (int kk = 0; kk < HPAD; kk += 4) {
                float4 hv = *reinterpret_cast<const float4*>(hb + kk);
                float4 wv = *reinterpret_cast<const float4*>(wfc_sh + kk);
                s0 = fmaf(hv.x, wv.x, s0);
                s1 = fmaf(hv.y, wv.y, s1);
                s2 = fmaf(hv.z, wv.z, s2);
                s3 = fmaf(hv.w, wv.w, s3);
            }
            yp[t] = (s0 + s1) + (s2 + s3) + bfc;
        }
    }
}

extern "C" void kernel_launch(void* const* d_in, const int* in_sizes, int n_in,
                              void* d_out, int out_size) {
    const float* input = (const float*)d_in[0];
    const float* W_ih  = (const float*)d_in[1];
    const float* W_hh  = (const float*)d_in[2];
    const float* b_ih  = (const float*)d_in[3];
    const float* b_hh  = (const float*)d_in[4];
    const float* W_fc  = (const float*)d_in[5];
    const float* b_fc  = (const float*)d_in[6];
    // d_in[7] = future (always 0 for this problem) — ignored.
    float* out = (float*)d_out;

    dim3 grid(BATCH / BT);   // 1024 CTAs
    dim3 block(NTHR);        // 204 threads
    lstm_kernel<<<grid, block>>>(input, W_ih, W_hh, b_ih, b_hh, W_fc, b_fc, out);
}